// round 1
// baseline (speedup 1.0000x reference)
#include <cuda_runtime.h>
#include <cstdint>

#define Bc 2
#define Cc 512
#define NHc 8
#define NPc 4
#define HDc 64
#define Dim 20
#define Nspat 8000          // 20*20*20
#define MTOT (Bc*Nspat)     // 16000
#define LN_EPS 1e-5f

// ---------------- scratch (no allocations allowed) ----------------
__device__ float g_mean[MTOT];
__device__ float g_rstd[MTOT];
__device__ float g_q   [(size_t)MTOT*Cc];          // normalized tokens (M,512)
__device__ float g_Q   [(size_t)MTOT*Cc];          // Q = q@Wq+bq
__device__ float g_hid [(size_t)MTOT*Cc];          // relu(Q@Wo1+bo1)
__device__ float g_off [(size_t)MTOT*NHc*NPc*3];   // clipped offsets
__device__ float g_attn[(size_t)MTOT*NHc*NPc];     // logits then softmax (in place)
__device__ float g_feats[(size_t)Bc*NHc*Nspat*HDc];// f_kv permuted (B,NH,D,H,W,HD)
__device__ float g_samp[(size_t)MTOT*Cc];          // attn-weighted samples (M,512)

// ---------------- 1) per-token mean / rstd ----------------
__global__ void k_stats(const float* __restrict__ fq) {
    int t = blockIdx.x * blockDim.x + threadIdx.x;
    if (t >= MTOT) return;
    int b = t / Nspat, n = t - b * Nspat;
    const float* p = fq + (size_t)b * Cc * Nspat + n;
    float s = 0.f, ss = 0.f;
    #pragma unroll 8
    for (int c = 0; c < Cc; ++c) {
        float v = p[(size_t)c * Nspat];
        s += v; ss += v * v;
    }
    float mu  = s * (1.f / Cc);
    float var = ss * (1.f / Cc) - mu * mu;
    g_mean[t] = mu;
    g_rstd[t] = rsqrtf(var + LN_EPS);
}

// ---------------- 2) transpose + layernorm -> g_q (M,C) ----------------
__global__ void k_lnT(const float* __restrict__ fq,
                      const float* __restrict__ lng,
                      const float* __restrict__ lnb) {
    __shared__ float tile[32][33];
    int b  = blockIdx.z;
    int n0 = blockIdx.x * 32;
    int c0 = blockIdx.y * 32;
    int tx = threadIdx.x, ty = threadIdx.y;  // (32,8)
    const float* src = fq + (size_t)b * Cc * Nspat;
    #pragma unroll
    for (int i = 0; i < 32; i += 8) {
        int c = c0 + ty + i, n = n0 + tx;
        tile[ty + i][tx] = src[(size_t)c * Nspat + n];
    }
    __syncthreads();
    #pragma unroll
    for (int i = 0; i < 32; i += 8) {
        int n = n0 + ty + i;
        int c = c0 + tx;
        int t = b * Nspat + n;
        float v = tile[tx][ty + i];
        g_q[(size_t)t * Cc + c] = (v - g_mean[t]) * g_rstd[t] * lng[c] + lnb[c];
    }
}

// ---------------- 3) permute f_kv (B,NH,HD,H,W,D) -> (B,NH,D,H,W,HD) ----------------
__global__ void k_perm(const float* __restrict__ fkv) {
    __shared__ float s[HDc * 21];   // [hd*21 + z], padded vs bank conflicts
    int blk = blockIdx.x;           // ((b*NH + h)*H + y)*W + x
    int x = blk % Dim;
    int y = (blk / Dim) % Dim;
    int h = (blk / (Dim * Dim)) % NHc;
    int b = blk / (Dim * Dim * NHc);
    const float* src = fkv + ((size_t)(b * Cc + h * HDc)) * Nspat + (y * Dim + x) * Dim;
    for (int idx = threadIdx.x; idx < HDc * Dim; idx += blockDim.x) {
        int hd = idx / Dim, z = idx - hd * Dim;
        s[hd * 21 + z] = src[(size_t)hd * Nspat + z];
    }
    __syncthreads();
    float* dst = g_feats + ((size_t)(b * NHc + h) * Nspat) * HDc;
    for (int idx = threadIdx.x; idx < HDc * Dim; idx += blockDim.x) {
        int z = idx / HDc, hd = idx - z * HDc;
        dst[(size_t)((z * Dim + y) * Dim + x) * HDc + hd] = s[hd * 21 + z];
    }
}

// ---------------- 4) fp32 SIMT GEMM: C = act(A(MxK) @ B(KxN) + bias) ----------------
// ACT: 0 none, 1 relu, 2 clip(-3,3). TROUT: write transposed to (B,C,Nspat).
template<int ACT, bool TROUT>
__global__ void __launch_bounds__(256) k_gemm(const float* __restrict__ A,
                                              const float* __restrict__ Bm,
                                              const float* __restrict__ bias,
                                              float* __restrict__ Cm,
                                              int M, int Nc, int K, int ldb) {
    __shared__ float As[8][128];
    __shared__ float Bs[8][128];
    int tid = threadIdx.x;
    int m0 = blockIdx.y * 128;
    int n0 = blockIdx.x * 128;
    int tr = tid >> 4;       // 0..15
    int tc = tid & 15;       // 0..15

    float acc[8][8];
    #pragma unroll
    for (int i = 0; i < 8; ++i)
        #pragma unroll
        for (int j = 0; j < 8; ++j) acc[i][j] = 0.f;

    int arow = tid >> 1;            // 0..127
    int acol = (tid & 1) * 4;
    int brow = tid >> 5;            // 0..7
    int bcol = (tid & 31) * 4;

    bool aok = (m0 + arow) < M;
    const float* Aptr = A + (size_t)(m0 + arow) * K + acol;
    bool bok = (n0 + bcol) < Nc;    // Nc is always a multiple of 4 here
    const float* Bptr = Bm + (size_t)brow * ldb + n0 + bcol;

    for (int k0 = 0; k0 < K; k0 += 8) {
        float4 av = aok ? *(const float4*)(Aptr + k0) : make_float4(0,0,0,0);
        As[acol + 0][arow] = av.x;
        As[acol + 1][arow] = av.y;
        As[acol + 2][arow] = av.z;
        As[acol + 3][arow] = av.w;
        float4 bv = bok ? *(const float4*)(Bptr + (size_t)k0 * ldb) : make_float4(0,0,0,0);
        *(float4*)&Bs[brow][bcol] = bv;
        __syncthreads();
        #pragma unroll
        for (int kk = 0; kk < 8; ++kk) {
            float4 a0 = *(const float4*)&As[kk][tr * 8];
            float4 a1 = *(const float4*)&As[kk][tr * 8 + 4];
            float4 b0 = *(const float4*)&Bs[kk][tc * 8];
            float4 b1 = *(const float4*)&Bs[kk][tc * 8 + 4];
            float am[8] = {a0.x,a0.y,a0.z,a0.w,a1.x,a1.y,a1.z,a1.w};
            float bn[8] = {b0.x,b0.y,b0.z,b0.w,b1.x,b1.y,b1.z,b1.w};
            #pragma unroll
            for (int i = 0; i < 8; ++i)
                #pragma unroll
                for (int j = 0; j < 8; ++j)
                    acc[i][j] += am[i] * bn[j];
        }
        __syncthreads();
    }

    #pragma unroll
    for (int i = 0; i < 8; ++i) {
        int row = m0 + tr * 8 + i;
        if (row >= M) continue;
        #pragma unroll
        for (int j = 0; j < 8; ++j) {
            int col = n0 + tc * 8 + j;
            if (col < Nc) {
                float v = acc[i][j] + bias[col];
                if (ACT == 1) v = fmaxf(v, 0.f);
                if (ACT == 2) v = fminf(fmaxf(v, -3.f), 3.f);
                if (TROUT) {
                    int b = row / Nspat;
                    int n = row - b * Nspat;
                    Cm[((size_t)(b * Cc + col)) * Nspat + n] = v;
                } else {
                    Cm[(size_t)row * Nc + col] = v;
                }
            }
        }
    }
}

// ---------------- 5) softmax over NP=4 (in place on g_attn) ----------------
__global__ void k_softmax() {
    int i = blockIdx.x * blockDim.x + threadIdx.x;   // over MTOT*NH groups
    if (i >= MTOT * NHc) return;
    float4 v = ((const float4*)g_attn)[i];
    float m = fmaxf(fmaxf(v.x, v.y), fmaxf(v.z, v.w));
    float e0 = __expf(v.x - m), e1 = __expf(v.y - m);
    float e2 = __expf(v.z - m), e3 = __expf(v.w - m);
    float inv = 1.f / (e0 + e1 + e2 + e3);
    ((float4*)g_attn)[i] = make_float4(e0 * inv, e1 * inv, e2 * inv, e3 * inv);
}

// ---------------- 6) trilinear gather + attention-weighted sum ----------------
// one warp per (b,n,h); lane covers channels {lane, lane+32}
__global__ void k_sample() {
    int gw   = (blockIdx.x * blockDim.x + threadIdx.x) >> 5;
    int lane = threadIdx.x & 31;
    if (gw >= MTOT * NHc) return;
    int h = gw % NHc;
    int t = gw / NHc;
    int b = t / Nspat;
    int n = t - b * Nspat;
    int y = n / (Dim * Dim);
    int x = (n / Dim) % Dim;
    int z = n % Dim;

    const float* off  = g_off  + (size_t)gw * NPc * 3;
    const float* attn = g_attn + (size_t)gw * NPc;
    const float* feats = g_feats + ((size_t)(b * NHc + h) * Nspat) * HDc;

    float acc0 = 0.f, acc1 = 0.f;
    #pragma unroll
    for (int p = 0; p < NPc; ++p) {
        float ap = attn[p];
        // ref: grid ch0 (base gy) -> W axis, ch1 (gx) -> H axis, ch2 (gz) -> D axis; H==W==D so scale==1
        float ix = fminf(fmaxf((float)y + off[p * 3 + 0], 0.f), (float)(Dim - 1));
        float iy = fminf(fmaxf((float)x + off[p * 3 + 1], 0.f), (float)(Dim - 1));
        float iz = fminf(fmaxf((float)z + off[p * 3 + 2], 0.f), (float)(Dim - 1));
        float x0f = floorf(ix), y0f = floorf(iy), z0f = floorf(iz);
        float fx = ix - x0f, fy = iy - y0f, fz = iz - z0f;
        int x0 = (int)x0f, y0 = (int)y0f, z0 = (int)z0f;
        int x1 = min(x0 + 1, Dim - 1);
        int y1 = min(y0 + 1, Dim - 1);
        int z1 = min(z0 + 1, Dim - 1);
        float wx[2] = {1.f - fx, fx};
        float wy[2] = {1.f - fy, fy};
        float wz[2] = {1.f - fz, fz};
        int   xs[2] = {x0, x1}, ys[2] = {y0, y1}, zs[2] = {z0, z1};
        #pragma unroll
        for (int dz = 0; dz < 2; ++dz)
            #pragma unroll
            for (int dy = 0; dy < 2; ++dy)
                #pragma unroll
                for (int dx = 0; dx < 2; ++dx) {
                    float w = ap * wz[dz] * wy[dy] * wx[dx];
                    const float* f = feats + (size_t)((zs[dz] * Dim + ys[dy]) * Dim + xs[dx]) * HDc;
                    acc0 += w * f[lane];
                    acc1 += w * f[lane + 32];
                }
    }
    float* o = g_samp + (size_t)t * Cc + h * HDc;
    o[lane]      = acc0;
    o[lane + 32] = acc1;
}

// ---------------- host ----------------
extern "C" void kernel_launch(void* const* d_in, const int* in_sizes, int n_in,
                              void* d_out, int out_size) {
    (void)in_sizes; (void)n_in; (void)out_size;
    const float* f_query = (const float*)d_in[0];
    const float* f_kv    = (const float*)d_in[1];
    const float* ln_g    = (const float*)d_in[2];
    const float* ln_b    = (const float*)d_in[3];
    const float* Wq   = (const float*)d_in[4];
    const float* bq   = (const float*)d_in[5];
    const float* Wo1  = (const float*)d_in[6];
    const float* bo1  = (const float*)d_in[7];
    const float* Wo2  = (const float*)d_in[8];
    const float* bo2  = (const float*)d_in[9];
    const float* Wa   = (const float*)d_in[10];
    const float* ba   = (const float*)d_in[11];
    const float* Wout = (const float*)d_in[12];
    const float* bout = (const float*)d_in[13];
    float* out = (float*)d_out;

    float *p_q, *p_Q, *p_hid, *p_off, *p_attn, *p_samp;
    cudaGetSymbolAddress((void**)&p_q,    g_q);
    cudaGetSymbolAddress((void**)&p_Q,    g_Q);
    cudaGetSymbolAddress((void**)&p_hid,  g_hid);
    cudaGetSymbolAddress((void**)&p_off,  g_off);
    cudaGetSymbolAddress((void**)&p_attn, g_attn);
    cudaGetSymbolAddress((void**)&p_samp, g_samp);

    // 1) LN stats
    k_stats<<<(MTOT + 255) / 256, 256>>>(f_query);
    // 2) transpose + normalize
    k_lnT<<<dim3(Nspat / 32, Cc / 32, Bc), dim3(32, 8)>>>(f_query, ln_g, ln_b);
    // 3) permute KV to channels-last
    k_perm<<<Bc * NHc * Dim * Dim, 256>>>(f_kv);
    // 4) Q = q @ Wq + bq
    k_gemm<0, false><<<dim3(4, MTOT / 128), 256>>>(p_q, Wq, bq, p_Q, MTOT, Cc, Cc, Cc);
    // 5) hid = relu(Q @ Wo1 + bo1)
    k_gemm<1, false><<<dim3(4, MTOT / 128), 256>>>(p_Q, Wo1, bo1, p_hid, MTOT, Cc, Cc, Cc);
    // 6) off = clip(hid @ Wo2 + bo2, -3, 3)   (N = NH*NP*3 = 96)
    k_gemm<2, false><<<dim3(1, MTOT / 128), 256>>>(p_hid, Wo2, bo2, p_off, MTOT, NHc * NPc * 3, Cc, NHc * NPc * 3);
    // 7) attn logits = Q @ Wa + ba            (N = NH*NP = 32)
    k_gemm<0, false><<<dim3(1, MTOT / 128), 256>>>(p_Q, Wa, ba, p_attn, MTOT, NHc * NPc, Cc, NHc * NPc);
    // 8) softmax over NP
    k_softmax<<<(MTOT * NHc + 255) / 256, 256>>>();
    // 9) trilinear sampling + attention weighting
    k_sample<<<(MTOT * NHc) * 32 / 256, 256>>>();
    // 10) out = (samp @ Wout + bout), written transposed to (B,C,H,W,D)
    k_gemm<0, true><<<dim3(4, MTOT / 128), 256>>>(p_samp, Wout, bout, out, MTOT, Cc, Cc, Cc);
}

// round 3
// speedup vs baseline: 2.0949x; 2.0949x over previous
#include <cuda_runtime.h>
#include <cuda_bf16.h>
#include <cstdint>

#define Bc 2
#define Cc 512
#define NHc 8
#define NPc 4
#define HDc 64
#define Dim 20
#define Nspat 8000          // 20*20*20
#define MTOT (Bc*Nspat)     // 16000
#define LN_EPS 1e-5f

// ---------------- scratch (no allocations allowed) ----------------
__device__ float g_mean[MTOT];
__device__ float g_rstd[MTOT];
__device__ __align__(16) float g_q   [(size_t)MTOT*Cc];
__device__ __align__(16) float g_Q   [(size_t)MTOT*Cc];
__device__ __align__(16) float g_hid [(size_t)MTOT*Cc];
__device__ __align__(16) float g_off [(size_t)MTOT*NHc*NPc*3];
__device__ __align__(16) float g_attn[(size_t)MTOT*NHc*NPc];
__device__ __align__(16) float g_feats[(size_t)Bc*NHc*Nspat*HDc];
__device__ __align__(16) float g_samp[(size_t)MTOT*Cc];
// split/transposed weights: (Npad, 512) K-major, hi/lo bf16
__device__ __align__(256) __nv_bfloat16 g_WqH  [512*512];
__device__ __align__(256) __nv_bfloat16 g_WqL  [512*512];
__device__ __align__(256) __nv_bfloat16 g_Wo1H [512*512];
__device__ __align__(256) __nv_bfloat16 g_Wo1L [512*512];
__device__ __align__(256) __nv_bfloat16 g_WoutH[512*512];
__device__ __align__(256) __nv_bfloat16 g_WoutL[512*512];
__device__ __align__(256) __nv_bfloat16 g_Wo2H [128*512];
__device__ __align__(256) __nv_bfloat16 g_Wo2L [128*512];
__device__ __align__(256) __nv_bfloat16 g_WaH  [128*512];
__device__ __align__(256) __nv_bfloat16 g_WaL  [128*512];

// ================= helpers =================
__device__ __forceinline__ uint32_t smem_u32(const void* p) {
    uint32_t a;
    asm("{ .reg .u64 t; cvta.to.shared.u64 t, %1; cvt.u32.u64 %0, t; }" : "=r"(a) : "l"(p));
    return a;
}
__device__ __forceinline__ void ldsm4(uint32_t* r, uint32_t addr) {
    asm volatile("ldmatrix.sync.aligned.m8n8.x4.shared.b16 {%0,%1,%2,%3}, [%4];"
        : "=r"(r[0]), "=r"(r[1]), "=r"(r[2]), "=r"(r[3]) : "r"(addr));
}
__device__ __forceinline__ void mma_bf16(float* c, const uint32_t* a, const uint32_t* b) {
    asm volatile(
        "mma.sync.aligned.m16n8k16.row.col.f32.bf16.bf16.f32 "
        "{%0,%1,%2,%3}, {%4,%5,%6,%7}, {%8,%9}, {%0,%1,%2,%3};"
        : "+f"(c[0]), "+f"(c[1]), "+f"(c[2]), "+f"(c[3])
        : "r"(a[0]), "r"(a[1]), "r"(a[2]), "r"(a[3]), "r"(b[0]), "r"(b[1]));
}
#define CPA16(dst, src) \
    asm volatile("cp.async.cg.shared.global [%0], [%1], 16;" :: "r"(dst), "l"(src) : "memory")

// ================= split-bf16 HMMA GEMM =================
// D = act(A(M,512)@W(512,Nc)+bias). W pre-transposed/split: (Npad,512) K-major hi/lo.
// Tile 128x128, BK=32, double-buffered. 3 MMAs per product: hh + lh + hl.
// smem per stage: Ah 10KB | Al 10KB | Bh 10KB | Bl 10KB  (rows: 80B stride = 40 bf16)
#define MG_STAGE 40960
#define MG_SMEM  (2*MG_STAGE)   // 80KB dynamic

template<int ACT, bool TROUT>
__global__ void __launch_bounds__(256, 1) k_mgemm(
    const float* __restrict__ A,
    const __nv_bfloat16* __restrict__ BH,
    const __nv_bfloat16* __restrict__ BL,
    const float* __restrict__ bias,
    float* __restrict__ Cm, int Nc)
{
    extern __shared__ __align__(1024) char sm[];
    const uint32_t smb = smem_u32(sm);
    const int tid = threadIdx.x;
    const int wid = tid >> 5, lane = tid & 31;
    const int m0 = blockIdx.y * 128;
    const int n0 = blockIdx.x * 128;
    const int wm = wid >> 1;   // 0..3 -> m offset wm*32
    const int wn = wid & 1;    // 0..1 -> n offset wn*64

    // ldmatrix per-lane offsets
    const int tq = lane >> 3, rr = lane & 7;
    const int a_row = rr + (tq & 1) * 8;       // within 16-row tile
    const int a_col = (tq >> 1) * 8;           // 0 or 8
    const int b_row = rr + (tq >> 1) * 8;
    const int b_col = (tq & 1) * 8;

    // loader indices
    const int ar = tid >> 1;               // A row 0..127
    const int ac = (tid & 1) * 16;         // A col base 0 or 16
    const int bn = tid >> 1;               // B n-row 0..127
    const int bk = (tid & 1) * 16;         // B k base 0 or 16

    const float* Aptr = A + (size_t)(m0 + ar) * 512 + ac;
    const __nv_bfloat16* BHp = BH + (size_t)(n0 + bn) * 512 + bk;
    const __nv_bfloat16* BLp = BL + (size_t)(n0 + bn) * 512 + bk;

    float4 areg[4];
    auto ldgA = [&](int kt) {
        const float4* p = (const float4*)(Aptr + kt * 32);
        #pragma unroll
        for (int i = 0; i < 4; ++i) areg[i] = p[i];
    };
    auto stsA = [&](int stage) {
        uint32_t hbase = smb + stage * MG_STAGE + ar * 80 + ac * 2;
        uint32_t lbase = hbase + 10240;
        #pragma unroll
        for (int i = 0; i < 4; ++i) {
            float4 v = areg[i];
            uint32_t bx = __float_as_uint(v.x), by = __float_as_uint(v.y);
            uint32_t bz = __float_as_uint(v.z), bw = __float_as_uint(v.w);
            uint32_t h0 = __byte_perm(bx, by, 0x7632);
            uint32_t h1 = __byte_perm(bz, bw, 0x7632);
            float lx = v.x - __uint_as_float(bx & 0xFFFF0000u);
            float ly = v.y - __uint_as_float(by & 0xFFFF0000u);
            float lz = v.z - __uint_as_float(bz & 0xFFFF0000u);
            float lw = v.w - __uint_as_float(bw & 0xFFFF0000u);
            __nv_bfloat162 l01 = __float22bfloat162_rn(make_float2(lx, ly));
            __nv_bfloat162 l23 = __float22bfloat162_rn(make_float2(lz, lw));
            *(uint2*)(sm + (hbase - smb) + i * 8) = make_uint2(h0, h1);
            *(uint2*)(sm + (lbase - smb) + i * 8) = make_uint2(*(uint32_t*)&l01, *(uint32_t*)&l23);
        }
    };
    auto ldB = [&](int stage, int kt) {
        uint32_t hb = smb + stage * MG_STAGE + 20480 + bn * 80 + bk * 2;
        uint32_t lb = hb + 10240;
        CPA16(hb,      BHp + kt * 32);
        CPA16(hb + 16, BHp + kt * 32 + 8);
        CPA16(lb,      BLp + kt * 32);
        CPA16(lb + 16, BLp + kt * 32 + 8);
        asm volatile("cp.async.commit_group;" ::: "memory");
    };

    float acc[2][8][4];
    #pragma unroll
    for (int mi = 0; mi < 2; ++mi)
        #pragma unroll
        for (int j = 0; j < 8; ++j)
            #pragma unroll
            for (int q = 0; q < 4; ++q) acc[mi][j][q] = 0.f;

    // prologue: stage 0
    ldB(0, 0);
    ldgA(0);
    stsA(0);
    asm volatile("cp.async.wait_group 0;" ::: "memory");
    __syncthreads();

    for (int kt = 0; kt < 16; ++kt) {
        int cur = kt & 1, nxt = cur ^ 1;
        if (kt + 1 < 16) {
            ldB(nxt, kt + 1);
            ldgA(kt + 1);
        }
        uint32_t abase = smb + cur * MG_STAGE;
        uint32_t bbase = abase + 20480;
        #pragma unroll
        for (int ks = 0; ks < 2; ++ks) {
            int kc = ks * 16;
            uint32_t ah[2][4], al[2][4], bh[4][4], bl[4][4];
            #pragma unroll
            for (int mi = 0; mi < 2; ++mi) {
                uint32_t ad = abase + (uint32_t)(wm * 32 + mi * 16 + a_row) * 80 + (kc + a_col) * 2;
                ldsm4(ah[mi], ad);
                ldsm4(al[mi], ad + 10240);
            }
            #pragma unroll
            for (int p = 0; p < 4; ++p) {
                uint32_t bd = bbase + (uint32_t)(wn * 64 + p * 16 + b_row) * 80 + (kc + b_col) * 2;
                ldsm4(bh[p], bd);
                ldsm4(bl[p], bd + 10240);
            }
            #pragma unroll
            for (int mi = 0; mi < 2; ++mi)
                #pragma unroll
                for (int j = 0; j < 8; ++j) {
                    const uint32_t* bhp = &bh[j >> 1][(j & 1) * 2];
                    const uint32_t* blp = &bl[j >> 1][(j & 1) * 2];
                    mma_bf16(acc[mi][j], ah[mi], bhp);
                    mma_bf16(acc[mi][j], al[mi], bhp);
                    mma_bf16(acc[mi][j], ah[mi], blp);
                }
        }
        if (kt + 1 < 16) {
            stsA(nxt);
            asm volatile("cp.async.wait_group 0;" ::: "memory");
        }
        __syncthreads();
    }

    // epilogue
    #pragma unroll
    for (int mi = 0; mi < 2; ++mi) {
        int row0 = m0 + wm * 32 + mi * 16 + (lane >> 2);
        #pragma unroll
        for (int j = 0; j < 8; ++j) {
            int col0 = n0 + wn * 64 + j * 8 + (lane & 3) * 2;
            if (col0 >= Nc) continue;
            float b0 = bias[col0], b1 = bias[col0 + 1];
            #pragma unroll
            for (int half = 0; half < 2; ++half) {
                int row = row0 + half * 8;
                float v0 = acc[mi][j][half * 2 + 0] + b0;
                float v1 = acc[mi][j][half * 2 + 1] + b1;
                if (ACT == 1) { v0 = fmaxf(v0, 0.f); v1 = fmaxf(v1, 0.f); }
                if (ACT == 2) {
                    v0 = fminf(fmaxf(v0, -3.f), 3.f);
                    v1 = fminf(fmaxf(v1, -3.f), 3.f);
                }
                if (TROUT) {
                    int b = row / Nspat, n = row - b * Nspat;
                    Cm[((size_t)(b * Cc + col0)) * Nspat + n] = v0;
                    Cm[((size_t)(b * Cc + col0 + 1)) * Nspat + n] = v1;
                } else {
                    *(float2*)(Cm + (size_t)row * Nc + col0) = make_float2(v0, v1);
                }
            }
        }
    }
}

// ---------------- weight prep: transpose + split (K,Nc) -> (Npad,512) hi/lo ----------------
__global__ void k_wprep(const float* __restrict__ W,
                        __nv_bfloat16* __restrict__ WtH,
                        __nv_bfloat16* __restrict__ WtL, int Ncols) {
    __shared__ float t[32][33];
    int k0 = blockIdx.y * 32, n0 = blockIdx.x * 32;
    int tx = threadIdx.x, ty = threadIdx.y;  // (32,8)
    #pragma unroll
    for (int i = 0; i < 32; i += 8) {
        int k = k0 + ty + i, n = n0 + tx;
        t[ty + i][tx] = (n < Ncols) ? W[(size_t)k * Ncols + n] : 0.f;
    }
    __syncthreads();
    #pragma unroll
    for (int i = 0; i < 32; i += 8) {
        int n = n0 + ty + i, k = k0 + tx;
        float v = t[tx][ty + i];
        uint32_t b = __float_as_uint(v);
        float hv = __uint_as_float(b & 0xFFFF0000u);
        WtH[(size_t)n * 512 + k] = __ushort_as_bfloat16((unsigned short)(b >> 16));
        WtL[(size_t)n * 512 + k] = __float2bfloat16(v - hv);
    }
}

// ---------------- 1) per-token mean / rstd ----------------
__global__ void k_stats(const float* __restrict__ fq) {
    int t = blockIdx.x * blockDim.x + threadIdx.x;
    if (t >= MTOT) return;
    int b = t / Nspat, n = t - b * Nspat;
    const float* p = fq + (size_t)b * Cc * Nspat + n;
    float s = 0.f, ss = 0.f;
    #pragma unroll 8
    for (int c = 0; c < Cc; ++c) {
        float v = p[(size_t)c * Nspat];
        s += v; ss += v * v;
    }
    float mu  = s * (1.f / Cc);
    float var = ss * (1.f / Cc) - mu * mu;
    g_mean[t] = mu;
    g_rstd[t] = rsqrtf(var + LN_EPS);
}

// ---------------- 2) transpose + layernorm -> g_q (M,C) ----------------
__global__ void k_lnT(const float* __restrict__ fq,
                      const float* __restrict__ lng,
                      const float* __restrict__ lnb) {
    __shared__ float tile[32][33];
    int b  = blockIdx.z;
    int n0 = blockIdx.x * 32;
    int c0 = blockIdx.y * 32;
    int tx = threadIdx.x, ty = threadIdx.y;  // (32,8)
    const float* src = fq + (size_t)b * Cc * Nspat;
    #pragma unroll
    for (int i = 0; i < 32; i += 8) {
        int c = c0 + ty + i, n = n0 + tx;
        tile[ty + i][tx] = src[(size_t)c * Nspat + n];
    }
    __syncthreads();
    #pragma unroll
    for (int i = 0; i < 32; i += 8) {
        int n = n0 + ty + i;
        int c = c0 + tx;
        int t = b * Nspat + n;
        float v = tile[tx][ty + i];
        g_q[(size_t)t * Cc + c] = (v - g_mean[t]) * g_rstd[t] * lng[c] + lnb[c];
    }
}

// ---------------- 3) permute f_kv (B,NH,HD,H,W,D) -> (B,NH,D,H,W,HD) ----------------
__global__ void k_perm(const float* __restrict__ fkv) {
    __shared__ float s[HDc * 21];
    int blk = blockIdx.x;
    int x = blk % Dim;
    int y = (blk / Dim) % Dim;
    int h = (blk / (Dim * Dim)) % NHc;
    int b = blk / (Dim * Dim * NHc);
    const float* src = fkv + ((size_t)(b * Cc + h * HDc)) * Nspat + (y * Dim + x) * Dim;
    for (int idx = threadIdx.x; idx < HDc * Dim; idx += blockDim.x) {
        int hd = idx / Dim, z = idx - hd * Dim;
        s[hd * 21 + z] = src[(size_t)hd * Nspat + z];
    }
    __syncthreads();
    float* dst = g_feats + ((size_t)(b * NHc + h) * Nspat) * HDc;
    for (int idx = threadIdx.x; idx < HDc * Dim; idx += blockDim.x) {
        int z = idx / HDc, hd = idx - z * HDc;
        dst[(size_t)((z * Dim + y) * Dim + x) * HDc + hd] = s[hd * 21 + z];
    }
}

// ---------------- 5) softmax over NP=4 ----------------
__global__ void k_softmax() {
    int i = blockIdx.x * blockDim.x + threadIdx.x;
    if (i >= MTOT * NHc) return;
    float4 v = ((const float4*)g_attn)[i];
    float m = fmaxf(fmaxf(v.x, v.y), fmaxf(v.z, v.w));
    float e0 = __expf(v.x - m), e1 = __expf(v.y - m);
    float e2 = __expf(v.z - m), e3 = __expf(v.w - m);
    float inv = 1.f / (e0 + e1 + e2 + e3);
    ((float4*)g_attn)[i] = make_float4(e0 * inv, e1 * inv, e2 * inv, e3 * inv);
}

// ---------------- 6) trilinear gather + attention-weighted sum ----------------
__global__ void k_sample() {
    int gw   = (blockIdx.x * blockDim.x + threadIdx.x) >> 5;
    int lane = threadIdx.x & 31;
    if (gw >= MTOT * NHc) return;
    int h = gw % NHc;
    int t = gw / NHc;
    int b = t / Nspat;
    int n = t - b * Nspat;
    int y = n / (Dim * Dim);
    int x = (n / Dim) % Dim;
    int z = n % Dim;

    const float* off  = g_off  + (size_t)gw * NPc * 3;
    const float* attn = g_attn + (size_t)gw * NPc;
    const float* feats = g_feats + ((size_t)(b * NHc + h) * Nspat) * HDc;

    float acc0 = 0.f, acc1 = 0.f;
    #pragma unroll
    for (int p = 0; p < NPc; ++p) {
        float ap = attn[p];
        float ix = fminf(fmaxf((float)y + off[p * 3 + 0], 0.f), (float)(Dim - 1));
        float iy = fminf(fmaxf((float)x + off[p * 3 + 1], 0.f), (float)(Dim - 1));
        float iz = fminf(fmaxf((float)z + off[p * 3 + 2], 0.f), (float)(Dim - 1));
        float x0f = floorf(ix), y0f = floorf(iy), z0f = floorf(iz);
        float fx = ix - x0f, fy = iy - y0f, fz = iz - z0f;
        int x0 = (int)x0f, y0 = (int)y0f, z0 = (int)z0f;
        int x1 = min(x0 + 1, Dim - 1);
        int y1 = min(y0 + 1, Dim - 1);
        int z1 = min(z0 + 1, Dim - 1);
        float wx[2] = {1.f - fx, fx};
        float wy[2] = {1.f - fy, fy};
        float wz[2] = {1.f - fz, fz};
        int   xs[2] = {x0, x1}, ys[2] = {y0, y1}, zs[2] = {z0, z1};
        #pragma unroll
        for (int dz = 0; dz < 2; ++dz)
            #pragma unroll
            for (int dy = 0; dy < 2; ++dy)
                #pragma unroll
                for (int dx = 0; dx < 2; ++dx) {
                    float w = ap * wz[dz] * wy[dy] * wx[dx];
                    const float* f = feats + (size_t)((zs[dz] * Dim + ys[dy]) * Dim + xs[dx]) * HDc;
                    acc0 += w * f[lane];
                    acc1 += w * f[lane + 32];
                }
    }
    float* o = g_samp + (size_t)t * Cc + h * HDc;
    o[lane]      = acc0;
    o[lane + 32] = acc1;
}

// ---------------- host ----------------
extern "C" void kernel_launch(void* const* d_in, const int* in_sizes, int n_in,
                              void* d_out, int out_size) {
    (void)in_sizes; (void)n_in; (void)out_size;
    const float* f_query = (const float*)d_in[0];
    const float* f_kv    = (const float*)d_in[1];
    const float* ln_g    = (const float*)d_in[2];
    const float* ln_b    = (const float*)d_in[3];
    const float* Wq   = (const float*)d_in[4];
    const float* bq   = (const float*)d_in[5];
    const float* Wo1  = (const float*)d_in[6];
    const float* bo1  = (const float*)d_in[7];
    const float* Wo2  = (const float*)d_in[8];
    const float* bo2  = (const float*)d_in[9];
    const float* Wa   = (const float*)d_in[10];
    const float* ba   = (const float*)d_in[11];
    const float* Wout = (const float*)d_in[12];
    const float* bout = (const float*)d_in[13];
    float* out = (float*)d_out;

    float *p_q, *p_Q, *p_hid, *p_off, *p_attn, *p_samp;
    cudaGetSymbolAddress((void**)&p_q,    g_q);
    cudaGetSymbolAddress((void**)&p_Q,    g_Q);
    cudaGetSymbolAddress((void**)&p_hid,  g_hid);
    cudaGetSymbolAddress((void**)&p_off,  g_off);
    cudaGetSymbolAddress((void**)&p_attn, g_attn);
    cudaGetSymbolAddress((void**)&p_samp, g_samp);
    __nv_bfloat16 *wqH, *wqL, *wo1H, *wo1L, *wo2H, *wo2L, *waH, *waL, *woH, *woL;
    cudaGetSymbolAddress((void**)&wqH,  g_WqH);   cudaGetSymbolAddress((void**)&wqL,  g_WqL);
    cudaGetSymbolAddress((void**)&wo1H, g_Wo1H);  cudaGetSymbolAddress((void**)&wo1L, g_Wo1L);
    cudaGetSymbolAddress((void**)&wo2H, g_Wo2H);  cudaGetSymbolAddress((void**)&wo2L, g_Wo2L);
    cudaGetSymbolAddress((void**)&waH,  g_WaH);   cudaGetSymbolAddress((void**)&waL,  g_WaL);
    cudaGetSymbolAddress((void**)&woH,  g_WoutH); cudaGetSymbolAddress((void**)&woL,  g_WoutL);

    cudaFuncSetAttribute(k_mgemm<0,false>, cudaFuncAttributeMaxDynamicSharedMemorySize, MG_SMEM);
    cudaFuncSetAttribute(k_mgemm<1,false>, cudaFuncAttributeMaxDynamicSharedMemorySize, MG_SMEM);
    cudaFuncSetAttribute(k_mgemm<2,false>, cudaFuncAttributeMaxDynamicSharedMemorySize, MG_SMEM);
    cudaFuncSetAttribute(k_mgemm<0,true>,  cudaFuncAttributeMaxDynamicSharedMemorySize, MG_SMEM);

    // weight prep (transpose + split)
    k_wprep<<<dim3(16, 16), dim3(32, 8)>>>(Wq,   wqH,  wqL,  512);
    k_wprep<<<dim3(16, 16), dim3(32, 8)>>>(Wo1,  wo1H, wo1L, 512);
    k_wprep<<<dim3( 4, 16), dim3(32, 8)>>>(Wo2,  wo2H, wo2L, NHc * NPc * 3);
    k_wprep<<<dim3( 4, 16), dim3(32, 8)>>>(Wa,   waH,  waL,  NHc * NPc);
    k_wprep<<<dim3(16, 16), dim3(32, 8)>>>(Wout, woH,  woL,  512);

    // 1) LN stats
    k_stats<<<(MTOT + 255) / 256, 256>>>(f_query);
    // 2) transpose + normalize
    k_lnT<<<dim3(Nspat / 32, Cc / 32, Bc), dim3(32, 8)>>>(f_query, ln_g, ln_b);
    // 3) permute KV
    k_perm<<<Bc * NHc * Dim * Dim, 256>>>(f_kv);
    // 4) Q = q @ Wq + bq
    k_mgemm<0,false><<<dim3(4, 125), 256, MG_SMEM>>>(p_q, wqH, wqL, bq, p_Q, Cc);
    // 5) hid = relu(Q @ Wo1 + bo1)
    k_mgemm<1,false><<<dim3(4, 125), 256, MG_SMEM>>>(p_Q, wo1H, wo1L, bo1, p_hid, Cc);
    // 6) off = clip(hid @ Wo2 + bo2)
    k_mgemm<2,false><<<dim3(1, 125), 256, MG_SMEM>>>(p_hid, wo2H, wo2L, bo2, p_off, NHc * NPc * 3);
    // 7) attn logits
    k_mgemm<0,false><<<dim3(1, 125), 256, MG_SMEM>>>(p_Q, waH, waL, ba, p_attn, NHc * NPc);
    // 8) softmax
    k_softmax<<<(MTOT * NHc + 255) / 256, 256>>>();
    // 9) sampling
    k_sample<<<(MTOT * NHc) * 32 / 256, 256>>>();
    // 10) out = samp @ Wout + bout, transposed store
    k_mgemm<0,true><<<dim3(4, 125), 256, MG_SMEM>>>(p_samp, woH, woL, bout, out, Cc);
}

// round 5
// speedup vs baseline: 2.2755x; 1.0862x over previous
#include <cuda_runtime.h>
#include <cuda_bf16.h>
#include <cuda_fp16.h>
#include <cstdint>

#define Bc 2
#define Cc 512
#define NHc 8
#define NPc 4
#define HDc 64
#define Dim 20
#define Nspat 8000          // 20*20*20
#define MTOT (Bc*Nspat)     // 16000
#define LN_EPS 1e-5f

// ---------------- scratch (no allocations allowed) ----------------
__device__ __align__(16) float g_q   [(size_t)MTOT*Cc];
__device__ __align__(16) float g_Q   [(size_t)MTOT*Cc];
__device__ __align__(16) float g_hid [(size_t)MTOT*Cc];
__device__ __align__(16) float g_off [(size_t)MTOT*NHc*NPc*3];
__device__ __align__(16) float g_attn[(size_t)MTOT*NHc*NPc];
__device__ __align__(16) __half g_feats[(size_t)Bc*NHc*Nspat*HDc];
__device__ __align__(16) float g_samp[(size_t)MTOT*Cc];
// split/transposed weights: (Npad, 512) K-major, hi/lo bf16
__device__ __align__(256) __nv_bfloat16 g_WqH  [512*512];
__device__ __align__(256) __nv_bfloat16 g_WqL  [512*512];
__device__ __align__(256) __nv_bfloat16 g_Wo1H [512*512];
__device__ __align__(256) __nv_bfloat16 g_Wo1L [512*512];
__device__ __align__(256) __nv_bfloat16 g_WoutH[512*512];
__device__ __align__(256) __nv_bfloat16 g_WoutL[512*512];
__device__ __align__(256) __nv_bfloat16 g_Wo2H [128*512];
__device__ __align__(256) __nv_bfloat16 g_Wo2L [128*512];
__device__ __align__(256) __nv_bfloat16 g_WaH  [128*512];
__device__ __align__(256) __nv_bfloat16 g_WaL  [128*512];

// ================= helpers =================
__device__ __forceinline__ uint32_t smem_u32(const void* p) {
    uint32_t a;
    asm("{ .reg .u64 t; cvta.to.shared.u64 t, %1; cvt.u32.u64 %0, t; }" : "=r"(a) : "l"(p));
    return a;
}
__device__ __forceinline__ void ldsm4(uint32_t* r, uint32_t addr) {
    asm volatile("ldmatrix.sync.aligned.m8n8.x4.shared.b16 {%0,%1,%2,%3}, [%4];"
        : "=r"(r[0]), "=r"(r[1]), "=r"(r[2]), "=r"(r[3]) : "r"(addr));
}
__device__ __forceinline__ void mma_bf16(float* c, const uint32_t* a, const uint32_t* b) {
    asm volatile(
        "mma.sync.aligned.m16n8k16.row.col.f32.bf16.bf16.f32 "
        "{%0,%1,%2,%3}, {%4,%5,%6,%7}, {%8,%9}, {%0,%1,%2,%3};"
        : "+f"(c[0]), "+f"(c[1]), "+f"(c[2]), "+f"(c[3])
        : "r"(a[0]), "r"(a[1]), "r"(a[2]), "r"(a[3]), "r"(b[0]), "r"(b[1]));
}
#define CPA16(dst, src) \
    asm volatile("cp.async.cg.shared.global [%0], [%1], 16;" :: "r"(dst), "l"(src) : "memory")

// ================= split-bf16 HMMA GEMM body =================
// D = act(A(M,512)@W(512,Nc)+bias). W pre-transposed/split: (Npad,512) K-major hi/lo.
// Tile 128x128, BK=32, double-buffered. 3 MMAs: hh + lh + hl.
#define MG_STAGE 40960
#define MG_SMEM  (2*MG_STAGE)   // 80KB dynamic

__device__ __forceinline__ void mgemm_body(
    const float* __restrict__ A,
    const __nv_bfloat16* __restrict__ BH,
    const __nv_bfloat16* __restrict__ BL,
    const float* __restrict__ bias,
    float* __restrict__ Cm, int Nc, int act, bool trout,
    int m0, int n0, char* sm)
{
    const uint32_t smb = smem_u32(sm);
    const int tid = threadIdx.x;
    const int wid = tid >> 5, lane = tid & 31;
    const int wm = wid >> 1;
    const int wn = wid & 1;

    const int tq = lane >> 3, rr = lane & 7;
    const int a_row = rr + (tq & 1) * 8;
    const int a_col = (tq >> 1) * 8;
    const int b_row = rr + (tq >> 1) * 8;
    const int b_col = (tq & 1) * 8;

    const int ar = tid >> 1;
    const int ac = (tid & 1) * 16;
    const int bn = tid >> 1;
    const int bk = (tid & 1) * 16;

    const float* Aptr = A + (size_t)(m0 + ar) * 512 + ac;
    const __nv_bfloat16* BHp = BH + (size_t)(n0 + bn) * 512 + bk;
    const __nv_bfloat16* BLp = BL + (size_t)(n0 + bn) * 512 + bk;

    float4 areg[4];
    auto ldgA = [&](int kt) {
        const float4* p = (const float4*)(Aptr + kt * 32);
        #pragma unroll
        for (int i = 0; i < 4; ++i) areg[i] = p[i];
    };
    auto stsA = [&](int stage) {
        uint32_t hoff = stage * MG_STAGE + ar * 80 + ac * 2;
        #pragma unroll
        for (int i = 0; i < 4; ++i) {
            float4 v = areg[i];
            uint32_t bx = __float_as_uint(v.x), by = __float_as_uint(v.y);
            uint32_t bz = __float_as_uint(v.z), bw = __float_as_uint(v.w);
            uint32_t h0 = __byte_perm(bx, by, 0x7632);
            uint32_t h1 = __byte_perm(bz, bw, 0x7632);
            float lx = v.x - __uint_as_float(bx & 0xFFFF0000u);
            float ly = v.y - __uint_as_float(by & 0xFFFF0000u);
            float lz = v.z - __uint_as_float(bz & 0xFFFF0000u);
            float lw = v.w - __uint_as_float(bw & 0xFFFF0000u);
            __nv_bfloat162 l01 = __float22bfloat162_rn(make_float2(lx, ly));
            __nv_bfloat162 l23 = __float22bfloat162_rn(make_float2(lz, lw));
            *(uint2*)(sm + hoff + i * 8) = make_uint2(h0, h1);
            *(uint2*)(sm + hoff + 10240 + i * 8) = make_uint2(*(uint32_t*)&l01, *(uint32_t*)&l23);
        }
    };
    auto ldB = [&](int stage, int kt) {
        uint32_t hb = smb + stage * MG_STAGE + 20480 + bn * 80 + bk * 2;
        uint32_t lb = hb + 10240;
        CPA16(hb,      BHp + kt * 32);
        CPA16(hb + 16, BHp + kt * 32 + 8);
        CPA16(lb,      BLp + kt * 32);
        CPA16(lb + 16, BLp + kt * 32 + 8);
        asm volatile("cp.async.commit_group;" ::: "memory");
    };

    float acc[2][8][4];
    #pragma unroll
    for (int mi = 0; mi < 2; ++mi)
        #pragma unroll
        for (int j = 0; j < 8; ++j)
            #pragma unroll
            for (int q = 0; q < 4; ++q) acc[mi][j][q] = 0.f;

    ldB(0, 0);
    ldgA(0);
    stsA(0);
    asm volatile("cp.async.wait_group 0;" ::: "memory");
    __syncthreads();

    for (int kt = 0; kt < 16; ++kt) {
        int cur = kt & 1, nxt = cur ^ 1;
        if (kt + 1 < 16) {
            ldB(nxt, kt + 1);
            ldgA(kt + 1);
        }
        uint32_t abase = smb + cur * MG_STAGE;
        uint32_t bbase = abase + 20480;
        #pragma unroll
        for (int ks = 0; ks < 2; ++ks) {
            int kc = ks * 16;
            uint32_t ah[2][4], al[2][4], bh[4][4], bl[4][4];
            #pragma unroll
            for (int mi = 0; mi < 2; ++mi) {
                uint32_t ad = abase + (uint32_t)(wm * 32 + mi * 16 + a_row) * 80 + (kc + a_col) * 2;
                ldsm4(ah[mi], ad);
                ldsm4(al[mi], ad + 10240);
            }
            #pragma unroll
            for (int p = 0; p < 4; ++p) {
                uint32_t bd = bbase + (uint32_t)(wn * 64 + p * 16 + b_row) * 80 + (kc + b_col) * 2;
                ldsm4(bh[p], bd);
                ldsm4(bl[p], bd + 10240);
            }
            #pragma unroll
            for (int mi = 0; mi < 2; ++mi)
                #pragma unroll
                for (int j = 0; j < 8; ++j) {
                    const uint32_t* bhp = &bh[j >> 1][(j & 1) * 2];
                    const uint32_t* blp = &bl[j >> 1][(j & 1) * 2];
                    mma_bf16(acc[mi][j], ah[mi], bhp);
                    mma_bf16(acc[mi][j], al[mi], bhp);
                    mma_bf16(acc[mi][j], ah[mi], blp);
                }
        }
        if (kt + 1 < 16) {
            stsA(nxt);
            asm volatile("cp.async.wait_group 0;" ::: "memory");
        }
        __syncthreads();
    }

    #pragma unroll
    for (int mi = 0; mi < 2; ++mi) {
        int row0 = m0 + wm * 32 + mi * 16 + (lane >> 2);
        #pragma unroll
        for (int j = 0; j < 8; ++j) {
            int col0 = n0 + wn * 64 + j * 8 + (lane & 3) * 2;
            if (col0 >= Nc) continue;
            float b0 = bias[col0], b1 = bias[col0 + 1];
            #pragma unroll
            for (int half = 0; half < 2; ++half) {
                int row = row0 + half * 8;
                float v0 = acc[mi][j][half * 2 + 0] + b0;
                float v1 = acc[mi][j][half * 2 + 1] + b1;
                if (act == 1) { v0 = fmaxf(v0, 0.f); v1 = fmaxf(v1, 0.f); }
                if (act == 2) {
                    v0 = fminf(fmaxf(v0, -3.f), 3.f);
                    v1 = fminf(fmaxf(v1, -3.f), 3.f);
                }
                if (trout) {
                    int b = row / Nspat, n = row - b * Nspat;
                    Cm[((size_t)(b * Cc + col0)) * Nspat + n] = v0;
                    Cm[((size_t)(b * Cc + col0 + 1)) * Nspat + n] = v1;
                } else {
                    *(float2*)(Cm + (size_t)row * Nc + col0) = make_float2(v0, v1);
                }
            }
        }
    }
}

template<int ACT, bool TROUT>
__global__ void __launch_bounds__(256, 1) k_mgemm(
    const float* __restrict__ A,
    const __nv_bfloat16* __restrict__ BH,
    const __nv_bfloat16* __restrict__ BL,
    const float* __restrict__ bias,
    float* __restrict__ Cm, int Nc)
{
    extern __shared__ __align__(1024) char sm_dyn[];
    mgemm_body(A, BH, BL, bias, Cm, Nc, ACT, TROUT, blockIdx.y * 128, blockIdx.x * 128, sm_dyn);
}

// dual small GEMM: blocks [0,125) -> off=clip(hid@Wo2), [125,250) -> attn=Q@Wa
__global__ void __launch_bounds__(256, 1) k_mgemm_dual(
    const float* __restrict__ A1, const __nv_bfloat16* __restrict__ BH1,
    const __nv_bfloat16* __restrict__ BL1, const float* __restrict__ bias1,
    float* __restrict__ C1, int Nc1,
    const float* __restrict__ A2, const __nv_bfloat16* __restrict__ BH2,
    const __nv_bfloat16* __restrict__ BL2, const float* __restrict__ bias2,
    float* __restrict__ C2, int Nc2)
{
    extern __shared__ __align__(1024) char sm_dyn[];
    int by = blockIdx.y;
    if (by < 125)
        mgemm_body(A1, BH1, BL1, bias1, C1, Nc1, 2, false, by * 128, 0, sm_dyn);
    else
        mgemm_body(A2, BH2, BL2, bias2, C2, Nc2, 0, false, (by - 125) * 128, 0, sm_dyn);
}

// ---------------- merged weight prep ----------------
struct WPrepDesc {
    const float* W;
    __nv_bfloat16* H;
    __nv_bfloat16* L;
    int Ncols;
    int Npad;
};
__global__ void k_wprep_all(WPrepDesc w0, WPrepDesc w1, WPrepDesc w2, WPrepDesc w3, WPrepDesc w4) {
    WPrepDesc d;
    switch (blockIdx.z) {
        case 0: d = w0; break;
        case 1: d = w1; break;
        case 2: d = w2; break;
        case 3: d = w3; break;
        default: d = w4; break;
    }
    __shared__ float t[32][33];
    int k0 = blockIdx.y * 32, n0 = blockIdx.x * 32;
    if (n0 >= d.Npad) return;
    int tx = threadIdx.x, ty = threadIdx.y;  // (32,8)
    #pragma unroll
    for (int i = 0; i < 32; i += 8) {
        int k = k0 + ty + i, n = n0 + tx;
        t[ty + i][tx] = (n < d.Ncols) ? d.W[(size_t)k * d.Ncols + n] : 0.f;
    }
    __syncthreads();
    #pragma unroll
    for (int i = 0; i < 32; i += 8) {
        int n = n0 + ty + i, k = k0 + tx;
        float v = t[tx][ty + i];
        uint32_t b = __float_as_uint(v);
        float hv = __uint_as_float(b & 0xFFFF0000u);
        d.H[(size_t)n * 512 + k] = __ushort_as_bfloat16((unsigned short)(b >> 16));
        d.L[(size_t)n * 512 + k] = __float2bfloat16(v - hv);
    }
}

// ---------------- fused stats + transpose + layernorm -> g_q (M,C) ----------------
// block: 32 tokens x 512 channels. grid (250, B). dyn smem: 32*513 + 64 floats.
__global__ void __launch_bounds__(256) k_lnfuse(const float* __restrict__ fq,
                                                const float* __restrict__ lng,
                                                const float* __restrict__ lnb) {
    extern __shared__ __align__(1024) char sm_dyn[];
    float* sm = (float*)sm_dyn;
    float* smean = sm + 32 * 513;
    float* srstd = smean + 32;
    int b  = blockIdx.y;
    int n0 = blockIdx.x * 32;
    int tid = threadIdx.x;
    int warp = tid >> 5, lane = tid & 31;
    const float* src = fq + (size_t)b * Cc * Nspat + n0 + lane;
    #pragma unroll 8
    for (int it = 0; it < 64; ++it) {
        int c = it * 8 + warp;
        sm[lane * 513 + c] = src[(size_t)c * Nspat];
    }
    __syncthreads();
    #pragma unroll
    for (int i = 0; i < 4; ++i) {
        int tok = warp * 4 + i;
        float s = 0.f, ss = 0.f;
        const float* row = sm + tok * 513;
        #pragma unroll
        for (int j = 0; j < 16; ++j) {
            float v = row[lane + j * 32];
            s += v; ss += v * v;
        }
        #pragma unroll
        for (int o = 16; o > 0; o >>= 1) {
            s  += __shfl_xor_sync(0xffffffffu, s, o);
            ss += __shfl_xor_sync(0xffffffffu, ss, o);
        }
        if (lane == 0) {
            float mu = s * (1.f / Cc);
            float var = ss * (1.f / Cc) - mu * mu;
            smean[tok] = mu;
            srstd[tok] = rsqrtf(var + LN_EPS);
        }
    }
    __syncthreads();
    #pragma unroll
    for (int i = 0; i < 4; ++i) {
        int tok = warp * 4 + i;
        float mu = smean[tok], rs = srstd[tok];
        size_t obase = (size_t)(b * Nspat + n0 + tok) * Cc;
        const float* row = sm + tok * 513;
        #pragma unroll
        for (int k = 0; k < 4; ++k) {
            int c = lane * 4 + k * 128;
            float4 o;
            o.x = (row[c + 0] - mu) * rs * lng[c + 0] + lnb[c + 0];
            o.y = (row[c + 1] - mu) * rs * lng[c + 1] + lnb[c + 1];
            o.z = (row[c + 2] - mu) * rs * lng[c + 2] + lnb[c + 2];
            o.w = (row[c + 3] - mu) * rs * lng[c + 3] + lnb[c + 3];
            *(float4*)(g_q + obase + c) = o;
        }
    }
}

// ---------------- permute f_kv -> (B,NH,D,H,W,HD) as fp16 ----------------
__global__ void k_perm(const float* __restrict__ fkv) {
    __shared__ float s[HDc * 21];
    int blk = blockIdx.x;
    int x = blk % Dim;
    int y = (blk / Dim) % Dim;
    int h = (blk / (Dim * Dim)) % NHc;
    int b = blk / (Dim * Dim * NHc);
    const float* src = fkv + ((size_t)(b * Cc + h * HDc)) * Nspat + (y * Dim + x) * Dim;
    for (int idx = threadIdx.x; idx < HDc * Dim; idx += blockDim.x) {
        int hd = idx / Dim, z = idx - hd * Dim;
        s[hd * 21 + z] = src[(size_t)hd * Nspat + z];
    }
    __syncthreads();
    __half* dst = g_feats + ((size_t)(b * NHc + h) * Nspat) * HDc;
    for (int idx = threadIdx.x; idx < HDc * Dim; idx += blockDim.x) {
        int z = idx / HDc, hd = idx - z * HDc;
        dst[(size_t)((z * Dim + y) * Dim + x) * HDc + hd] = __float2half_rn(s[hd * 21 + z]);
    }
}

// ---------------- softmax over NP=4 ----------------
__global__ void k_softmax() {
    int i = blockIdx.x * blockDim.x + threadIdx.x;
    if (i >= MTOT * NHc) return;
    float4 v = ((const float4*)g_attn)[i];
    float m = fmaxf(fmaxf(v.x, v.y), fmaxf(v.z, v.w));
    float e0 = __expf(v.x - m), e1 = __expf(v.y - m);
    float e2 = __expf(v.z - m), e3 = __expf(v.w - m);
    float inv = 1.f / (e0 + e1 + e2 + e3);
    ((float4*)g_attn)[i] = make_float4(e0 * inv, e1 * inv, e2 * inv, e3 * inv);
}

// ---------------- trilinear gather + attention-weighted sum (fp16 feats) ----------------
__global__ void k_sample() {
    int gw   = (blockIdx.x * blockDim.x + threadIdx.x) >> 5;
    int lane = threadIdx.x & 31;
    if (gw >= MTOT * NHc) return;
    int h = gw % NHc;
    int t = gw / NHc;
    int b = t / Nspat;
    int n = t - b * Nspat;
    int y = n / (Dim * Dim);
    int x = (n / Dim) % Dim;
    int z = n % Dim;

    const float* off  = g_off  + (size_t)gw * NPc * 3;
    const float* attn = g_attn + (size_t)gw * NPc;
    const __half* feats = g_feats + ((size_t)(b * NHc + h) * Nspat) * HDc;

    float acc0 = 0.f, acc1 = 0.f;
    #pragma unroll
    for (int p = 0; p < NPc; ++p) {
        float ap = attn[p];
        float ix = fminf(fmaxf((float)y + off[p * 3 + 0], 0.f), (float)(Dim - 1));
        float iy = fminf(fmaxf((float)x + off[p * 3 + 1], 0.f), (float)(Dim - 1));
        float iz = fminf(fmaxf((float)z + off[p * 3 + 2], 0.f), (float)(Dim - 1));
        float x0f = floorf(ix), y0f = floorf(iy), z0f = floorf(iz);
        float fx = ix - x0f, fy = iy - y0f, fz = iz - z0f;
        int x0 = (int)x0f, y0 = (int)y0f, z0 = (int)z0f;
        int x1 = min(x0 + 1, Dim - 1);
        int y1 = min(y0 + 1, Dim - 1);
        int z1 = min(z0 + 1, Dim - 1);
        float wx[2] = {1.f - fx, fx};
        float wy[2] = {1.f - fy, fy};
        float wz[2] = {1.f - fz, fz};
        int   xs[2] = {x0, x1}, ys[2] = {y0, y1}, zs[2] = {z0, z1};
        #pragma unroll
        for (int dz = 0; dz < 2; ++dz)
            #pragma unroll
            for (int dy = 0; dy < 2; ++dy)
                #pragma unroll
                for (int dx = 0; dx < 2; ++dx) {
                    float w = ap * wz[dz] * wy[dy] * wx[dx];
                    const __half2* f = (const __half2*)(feats + (size_t)((zs[dz] * Dim + ys[dy]) * Dim + xs[dx]) * HDc);
                    float2 v = __half22float2(f[lane]);
                    acc0 += w * v.x;
                    acc1 += w * v.y;
                }
    }
    float* o = g_samp + (size_t)t * Cc + h * HDc + lane * 2;
    *(float2*)o = make_float2(acc0, acc1);
}

// ---------------- host ----------------
extern "C" void kernel_launch(void* const* d_in, const int* in_sizes, int n_in,
                              void* d_out, int out_size) {
    (void)in_sizes; (void)n_in; (void)out_size;
    const float* f_query = (const float*)d_in[0];
    const float* f_kv    = (const float*)d_in[1];
    const float* ln_g    = (const float*)d_in[2];
    const float* ln_b    = (const float*)d_in[3];
    const float* Wq   = (const float*)d_in[4];
    const float* bq   = (const float*)d_in[5];
    const float* Wo1  = (const float*)d_in[6];
    const float* bo1  = (const float*)d_in[7];
    const float* Wo2  = (const float*)d_in[8];
    const float* bo2  = (const float*)d_in[9];
    const float* Wa   = (const float*)d_in[10];
    const float* ba   = (const float*)d_in[11];
    const float* Wout = (const float*)d_in[12];
    const float* bout = (const float*)d_in[13];
    float* out = (float*)d_out;

    float *p_q, *p_Q, *p_hid, *p_off, *p_attn, *p_samp;
    cudaGetSymbolAddress((void**)&p_q,    g_q);
    cudaGetSymbolAddress((void**)&p_Q,    g_Q);
    cudaGetSymbolAddress((void**)&p_hid,  g_hid);
    cudaGetSymbolAddress((void**)&p_off,  g_off);
    cudaGetSymbolAddress((void**)&p_attn, g_attn);
    cudaGetSymbolAddress((void**)&p_samp, g_samp);
    __nv_bfloat16 *wqH, *wqL, *wo1H, *wo1L, *wo2H, *wo2L, *waH, *waL, *woH, *woL;
    cudaGetSymbolAddress((void**)&wqH,  g_WqH);   cudaGetSymbolAddress((void**)&wqL,  g_WqL);
    cudaGetSymbolAddress((void**)&wo1H, g_Wo1H);  cudaGetSymbolAddress((void**)&wo1L, g_Wo1L);
    cudaGetSymbolAddress((void**)&wo2H, g_Wo2H);  cudaGetSymbolAddress((void**)&wo2L, g_Wo2L);
    cudaGetSymbolAddress((void**)&waH,  g_WaH);   cudaGetSymbolAddress((void**)&waL,  g_WaL);
    cudaGetSymbolAddress((void**)&woH,  g_WoutH); cudaGetSymbolAddress((void**)&woL,  g_WoutL);

    cudaFuncSetAttribute(k_mgemm<0,false>, cudaFuncAttributeMaxDynamicSharedMemorySize, MG_SMEM);
    cudaFuncSetAttribute(k_mgemm<1,false>, cudaFuncAttributeMaxDynamicSharedMemorySize, MG_SMEM);
    cudaFuncSetAttribute(k_mgemm<0,true>,  cudaFuncAttributeMaxDynamicSharedMemorySize, MG_SMEM);
    cudaFuncSetAttribute(k_mgemm_dual,     cudaFuncAttributeMaxDynamicSharedMemorySize, MG_SMEM);
    const int LN_SMEM = (32 * 513 + 64) * 4;
    cudaFuncSetAttribute(k_lnfuse, cudaFuncAttributeMaxDynamicSharedMemorySize, LN_SMEM);

    // merged weight prep (transpose + split) — one launch
    WPrepDesc w0{Wq,   wqH,  wqL,  512, 512};
    WPrepDesc w1{Wo1,  wo1H, wo1L, 512, 512};
    WPrepDesc w2{Wout, woH,  woL,  512, 512};
    WPrepDesc w3{Wo2,  wo2H, wo2L, NHc * NPc * 3, 128};
    WPrepDesc w4{Wa,   waH,  waL,  NHc * NPc, 128};
    k_wprep_all<<<dim3(16, 16, 5), dim3(32, 8)>>>(w0, w1, w2, w3, w4);

    // fused stats + transpose + LN
    k_lnfuse<<<dim3(250, Bc), 256, LN_SMEM>>>(f_query, ln_g, ln_b);
    // permute KV to fp16 channels-last
    k_perm<<<Bc * NHc * Dim * Dim, 256>>>(f_kv);
    // Q = q @ Wq + bq
    k_mgemm<0,false><<<dim3(4, 125), 256, MG_SMEM>>>(p_q, wqH, wqL, bq, p_Q, Cc);
    // hid = relu(Q @ Wo1 + bo1)
    k_mgemm<1,false><<<dim3(4, 125), 256, MG_SMEM>>>(p_Q, wo1H, wo1L, bo1, p_hid, Cc);
    // off = clip(hid @ Wo2 + bo2)  AND  attn logits = Q @ Wa + ba  (one wave)
    k_mgemm_dual<<<dim3(1, 250), 256, MG_SMEM>>>(p_hid, wo2H, wo2L, bo2, p_off, NHc * NPc * 3,
                                                 p_Q,   waH,  waL,  ba,  p_attn, NHc * NPc);
    // softmax
    k_softmax<<<(MTOT * NHc + 255) / 256, 256>>>();
    // sampling
    k_sample<<<(MTOT * NHc) * 32 / 256, 256>>>();
    // out = samp @ Wout + bout, transposed store
    k_mgemm<0,true><<<dim3(4, 125), 256, MG_SMEM>>>(p_samp, woH, woL, bout, out, Cc);
}

// round 6
// speedup vs baseline: 2.3636x; 1.0387x over previous
#include <cuda_runtime.h>
#include <cuda_bf16.h>
#include <cuda_fp16.h>
#include <cstdint>

#define Bc 2
#define Cc 512
#define NHc 8
#define NPc 4
#define HDc 64
#define Dim 20
#define Nspat 8000          // 20*20*20
#define MTOT (Bc*Nspat)     // 16000
#define LN_EPS 1e-5f

// ---------------- scratch (no allocations allowed) ----------------
__device__ __align__(16) __nv_bfloat16 g_qH  [(size_t)MTOT*Cc];
__device__ __align__(16) __nv_bfloat16 g_qL  [(size_t)MTOT*Cc];
__device__ __align__(16) __nv_bfloat16 g_QH  [(size_t)MTOT*Cc];
__device__ __align__(16) __nv_bfloat16 g_QL  [(size_t)MTOT*Cc];
__device__ __align__(16) __nv_bfloat16 g_hidH[(size_t)MTOT*Cc];
__device__ __align__(16) __nv_bfloat16 g_hidL[(size_t)MTOT*Cc];
__device__ __align__(16) __nv_bfloat16 g_sH  [(size_t)MTOT*Cc];
__device__ __align__(16) __nv_bfloat16 g_sL  [(size_t)MTOT*Cc];
__device__ __align__(16) float g_off [(size_t)MTOT*NHc*NPc*3];
__device__ __align__(16) float g_attn[(size_t)MTOT*NHc*NPc];
__device__ __align__(16) __half g_feats[(size_t)Bc*NHc*Nspat*HDc];
// split/transposed weights: (Npad, 512) K-major, hi/lo bf16
__device__ __align__(256) __nv_bfloat16 g_WqH  [512*512];
__device__ __align__(256) __nv_bfloat16 g_WqL  [512*512];
__device__ __align__(256) __nv_bfloat16 g_Wo1H [512*512];
__device__ __align__(256) __nv_bfloat16 g_Wo1L [512*512];
__device__ __align__(256) __nv_bfloat16 g_WoutH[512*512];
__device__ __align__(256) __nv_bfloat16 g_WoutL[512*512];
__device__ __align__(256) __nv_bfloat16 g_Wo2H [128*512];
__device__ __align__(256) __nv_bfloat16 g_Wo2L [128*512];
__device__ __align__(256) __nv_bfloat16 g_WaH  [128*512];
__device__ __align__(256) __nv_bfloat16 g_WaL  [128*512];

// ================= helpers =================
__device__ __forceinline__ uint32_t smem_u32(const void* p) {
    uint32_t a;
    asm("{ .reg .u64 t; cvta.to.shared.u64 t, %1; cvt.u32.u64 %0, t; }" : "=r"(a) : "l"(p));
    return a;
}
__device__ __forceinline__ void ldsm4(uint32_t* r, uint32_t addr) {
    asm volatile("ldmatrix.sync.aligned.m8n8.x4.shared.b16 {%0,%1,%2,%3}, [%4];"
        : "=r"(r[0]), "=r"(r[1]), "=r"(r[2]), "=r"(r[3]) : "r"(addr));
}
__device__ __forceinline__ void mma_bf16(float* c, const uint32_t* a, const uint32_t* b) {
    asm volatile(
        "mma.sync.aligned.m16n8k16.row.col.f32.bf16.bf16.f32 "
        "{%0,%1,%2,%3}, {%4,%5,%6,%7}, {%8,%9}, {%0,%1,%2,%3};"
        : "+f"(c[0]), "+f"(c[1]), "+f"(c[2]), "+f"(c[3])
        : "r"(a[0]), "r"(a[1]), "r"(a[2]), "r"(a[3]), "r"(b[0]), "r"(b[1]));
}
#define CPA16(dst, src) \
    asm volatile("cp.async.cg.shared.global [%0], [%1], 16;" :: "r"(dst), "l"(src) : "memory")

// ================= split-bf16 HMMA GEMM (all operands pre-split) =================
// D = act(A(M,512)@W(512,Nc)+bias). A and W both (rows,512) K-major bf16 hi/lo.
// Tile 128x128, BK=32, 2-stage cp.async pipeline. 3 MMAs: hh + lh + hl.
// stage layout (80B row stride, 32 bf16/row): Ah@0 Al@10240 Bh@20480 Bl@30720
#define MG_STAGE 40960
#define MG_SMEM  (2*MG_STAGE)   // 80KB dynamic

// omode: 0 = fp32 row-major, 1 = fp32 transposed (B,C,Nspat), 2 = split bf16 H/L
__device__ __forceinline__ void sgemm_body(
    const __nv_bfloat16* __restrict__ AH, const __nv_bfloat16* __restrict__ AL,
    const __nv_bfloat16* __restrict__ BH, const __nv_bfloat16* __restrict__ BL,
    const float* __restrict__ bias,
    float* __restrict__ Cf, __nv_bfloat16* __restrict__ CH, __nv_bfloat16* __restrict__ CL,
    int Nc, int act, int omode, int m0, int n0, char* sm)
{
    const uint32_t smb = smem_u32(sm);
    const int tid = threadIdx.x;
    const int wid = tid >> 5, lane = tid & 31;
    const int wm = wid >> 1;
    const int wn = wid & 1;

    const int tq = lane >> 3, rr = lane & 7;
    const int a_row = rr + (tq & 1) * 8;
    const int a_col = (tq >> 1) * 8;
    const int b_row = rr + (tq >> 1) * 8;
    const int b_col = (tq & 1) * 8;

    const int r2  = tid >> 1;            // 0..127
    const int kc2 = (tid & 1) * 32;      // byte offset: 0 or 32

    const __nv_bfloat16* AHp = AH + (size_t)(m0 + r2) * 512 + (tid & 1) * 16;
    const __nv_bfloat16* ALp = AL + (size_t)(m0 + r2) * 512 + (tid & 1) * 16;
    const __nv_bfloat16* BHp = BH + (size_t)(n0 + r2) * 512 + (tid & 1) * 16;
    const __nv_bfloat16* BLp = BL + (size_t)(n0 + r2) * 512 + (tid & 1) * 16;

    auto ldAB = [&](int stage, int kt) {
        uint32_t ro = smb + stage * MG_STAGE + r2 * 80 + kc2;
        const int go = kt * 32;
        CPA16(ro,              AHp + go);
        CPA16(ro + 16,         AHp + go + 8);
        CPA16(ro + 10240,      ALp + go);
        CPA16(ro + 10240 + 16, ALp + go + 8);
        CPA16(ro + 20480,      BHp + go);
        CPA16(ro + 20480 + 16, BHp + go + 8);
        CPA16(ro + 30720,      BLp + go);
        CPA16(ro + 30720 + 16, BLp + go + 8);
        asm volatile("cp.async.commit_group;" ::: "memory");
    };

    float acc[2][8][4];
    #pragma unroll
    for (int mi = 0; mi < 2; ++mi)
        #pragma unroll
        for (int j = 0; j < 8; ++j)
            #pragma unroll
            for (int q = 0; q < 4; ++q) acc[mi][j][q] = 0.f;

    ldAB(0, 0);

    for (int kt = 0; kt < 16; ++kt) {
        int cur = kt & 1, nxt = cur ^ 1;
        if (kt + 1 < 16) {
            ldAB(nxt, kt + 1);
            asm volatile("cp.async.wait_group 1;" ::: "memory");
        } else {
            asm volatile("cp.async.wait_group 0;" ::: "memory");
        }
        __syncthreads();
        uint32_t abase = smb + cur * MG_STAGE;
        uint32_t bbase = abase + 20480;
        #pragma unroll
        for (int ks = 0; ks < 2; ++ks) {
            int kc = ks * 16;
            uint32_t ah[2][4], al[2][4], bh[4][4], bl[4][4];
            #pragma unroll
            for (int mi = 0; mi < 2; ++mi) {
                uint32_t ad = abase + (uint32_t)(wm * 32 + mi * 16 + a_row) * 80 + (kc + a_col) * 2;
                ldsm4(ah[mi], ad);
                ldsm4(al[mi], ad + 10240);
            }
            #pragma unroll
            for (int p = 0; p < 4; ++p) {
                uint32_t bd = bbase + (uint32_t)(wn * 64 + p * 16 + b_row) * 80 + (kc + b_col) * 2;
                ldsm4(bh[p], bd);
                ldsm4(bl[p], bd + 10240);
            }
            #pragma unroll
            for (int mi = 0; mi < 2; ++mi)
                #pragma unroll
                for (int j = 0; j < 8; ++j) {
                    const uint32_t* bhp = &bh[j >> 1][(j & 1) * 2];
                    const uint32_t* blp = &bl[j >> 1][(j & 1) * 2];
                    mma_bf16(acc[mi][j], ah[mi], bhp);
                    mma_bf16(acc[mi][j], al[mi], bhp);
                    mma_bf16(acc[mi][j], ah[mi], blp);
                }
        }
        __syncthreads();
    }

    #pragma unroll
    for (int mi = 0; mi < 2; ++mi) {
        int row0 = m0 + wm * 32 + mi * 16 + (lane >> 2);
        #pragma unroll
        for (int j = 0; j < 8; ++j) {
            int col0 = n0 + wn * 64 + j * 8 + (lane & 3) * 2;
            if (col0 >= Nc) continue;
            float b0 = bias[col0], b1 = bias[col0 + 1];
            #pragma unroll
            for (int half = 0; half < 2; ++half) {
                int row = row0 + half * 8;
                float v0 = acc[mi][j][half * 2 + 0] + b0;
                float v1 = acc[mi][j][half * 2 + 1] + b1;
                if (act == 1) { v0 = fmaxf(v0, 0.f); v1 = fmaxf(v1, 0.f); }
                if (act == 2) {
                    v0 = fminf(fmaxf(v0, -3.f), 3.f);
                    v1 = fminf(fmaxf(v1, -3.f), 3.f);
                }
                if (omode == 0) {
                    *(float2*)(Cf + (size_t)row * Nc + col0) = make_float2(v0, v1);
                } else if (omode == 1) {
                    int b = row / Nspat, n = row - b * Nspat;
                    Cf[((size_t)(b * Cc + col0)) * Nspat + n] = v0;
                    Cf[((size_t)(b * Cc + col0 + 1)) * Nspat + n] = v1;
                } else {
                    uint32_t u0 = __float_as_uint(v0), u1 = __float_as_uint(v1);
                    uint32_t hp = __byte_perm(u0, u1, 0x7632);
                    float l0 = v0 - __uint_as_float(u0 & 0xFFFF0000u);
                    float l1 = v1 - __uint_as_float(u1 & 0xFFFF0000u);
                    __nv_bfloat162 lp = __float22bfloat162_rn(make_float2(l0, l1));
                    *(uint32_t*)(CH + (size_t)row * Nc + col0) = hp;
                    *(uint32_t*)(CL + (size_t)row * Nc + col0) = *(uint32_t*)&lp;
                }
            }
        }
    }
}

template<int ACT, int OMODE>
__global__ void __launch_bounds__(256, 2) k_sgemm(
    const __nv_bfloat16* __restrict__ AH, const __nv_bfloat16* __restrict__ AL,
    const __nv_bfloat16* __restrict__ BH, const __nv_bfloat16* __restrict__ BL,
    const float* __restrict__ bias,
    float* __restrict__ Cf, __nv_bfloat16* __restrict__ CH, __nv_bfloat16* __restrict__ CL,
    int Nc)
{
    extern __shared__ __align__(1024) char sm_dyn[];
    sgemm_body(AH, AL, BH, BL, bias, Cf, CH, CL, Nc, ACT, OMODE,
               blockIdx.y * 128, blockIdx.x * 128, sm_dyn);
}

// dual small GEMM: blocks [0,125) -> off=clip(hid@Wo2), [125,250) -> attn=Q@Wa
__global__ void __launch_bounds__(256, 2) k_sgemm_dual(
    const __nv_bfloat16* __restrict__ A1H, const __nv_bfloat16* __restrict__ A1L,
    const __nv_bfloat16* __restrict__ B1H, const __nv_bfloat16* __restrict__ B1L,
    const float* __restrict__ bias1, float* __restrict__ C1, int Nc1,
    const __nv_bfloat16* __restrict__ A2H, const __nv_bfloat16* __restrict__ A2L,
    const __nv_bfloat16* __restrict__ B2H, const __nv_bfloat16* __restrict__ B2L,
    const float* __restrict__ bias2, float* __restrict__ C2, int Nc2)
{
    extern __shared__ __align__(1024) char sm_dyn[];
    int by = blockIdx.y;
    if (by < 125)
        sgemm_body(A1H, A1L, B1H, B1L, bias1, C1, nullptr, nullptr, Nc1, 2, 0, by * 128, 0, sm_dyn);
    else
        sgemm_body(A2H, A2L, B2H, B2L, bias2, C2, nullptr, nullptr, Nc2, 0, 0, (by - 125) * 128, 0, sm_dyn);
}

// ---------------- merged weight prep ----------------
struct WPrepDesc {
    const float* W;
    __nv_bfloat16* H;
    __nv_bfloat16* L;
    int Ncols;
    int Npad;
};
__global__ void k_wprep_all(WPrepDesc w0, WPrepDesc w1, WPrepDesc w2, WPrepDesc w3, WPrepDesc w4) {
    WPrepDesc d;
    switch (blockIdx.z) {
        case 0: d = w0; break;
        case 1: d = w1; break;
        case 2: d = w2; break;
        case 3: d = w3; break;
        default: d = w4; break;
    }
    __shared__ float t[32][33];
    int k0 = blockIdx.y * 32, n0 = blockIdx.x * 32;
    if (n0 >= d.Npad) return;
    int tx = threadIdx.x, ty = threadIdx.y;  // (32,8)
    #pragma unroll
    for (int i = 0; i < 32; i += 8) {
        int k = k0 + ty + i, n = n0 + tx;
        t[ty + i][tx] = (n < d.Ncols) ? d.W[(size_t)k * d.Ncols + n] : 0.f;
    }
    __syncthreads();
    #pragma unroll
    for (int i = 0; i < 32; i += 8) {
        int n = n0 + ty + i, k = k0 + tx;
        float v = t[tx][ty + i];
        uint32_t b = __float_as_uint(v);
        float hv = __uint_as_float(b & 0xFFFF0000u);
        d.H[(size_t)n * 512 + k] = __ushort_as_bfloat16((unsigned short)(b >> 16));
        d.L[(size_t)n * 512 + k] = __float2bfloat16(v - hv);
    }
}

// ---------------- fused stats + transpose + LN -> split qH/qL ----------------
__global__ void __launch_bounds__(256) k_lnfuse(const float* __restrict__ fq,
                                                const float* __restrict__ lng,
                                                const float* __restrict__ lnb) {
    extern __shared__ __align__(1024) char sm_dyn[];
    float* sm = (float*)sm_dyn;
    float* smean = sm + 32 * 513;
    float* srstd = smean + 32;
    int b  = blockIdx.y;
    int n0 = blockIdx.x * 32;
    int tid = threadIdx.x;
    int warp = tid >> 5, lane = tid & 31;
    const float* src = fq + (size_t)b * Cc * Nspat + n0 + lane;
    #pragma unroll 8
    for (int it = 0; it < 64; ++it) {
        int c = it * 8 + warp;
        sm[lane * 513 + c] = src[(size_t)c * Nspat];
    }
    __syncthreads();
    #pragma unroll
    for (int i = 0; i < 4; ++i) {
        int tok = warp * 4 + i;
        float s = 0.f, ss = 0.f;
        const float* row = sm + tok * 513;
        #pragma unroll
        for (int j = 0; j < 16; ++j) {
            float v = row[lane + j * 32];
            s += v; ss += v * v;
        }
        #pragma unroll
        for (int o = 16; o > 0; o >>= 1) {
            s  += __shfl_xor_sync(0xffffffffu, s, o);
            ss += __shfl_xor_sync(0xffffffffu, ss, o);
        }
        if (lane == 0) {
            float mu = s * (1.f / Cc);
            float var = ss * (1.f / Cc) - mu * mu;
            smean[tok] = mu;
            srstd[tok] = rsqrtf(var + LN_EPS);
        }
    }
    __syncthreads();
    #pragma unroll
    for (int i = 0; i < 4; ++i) {
        int tok = warp * 4 + i;
        float mu = smean[tok], rs = srstd[tok];
        size_t obase = (size_t)(b * Nspat + n0 + tok) * Cc;
        const float* row = sm + tok * 513;
        #pragma unroll
        for (int k = 0; k < 4; ++k) {
            int c = lane * 4 + k * 128;
            float v0 = (row[c + 0] - mu) * rs * lng[c + 0] + lnb[c + 0];
            float v1 = (row[c + 1] - mu) * rs * lng[c + 1] + lnb[c + 1];
            float v2 = (row[c + 2] - mu) * rs * lng[c + 2] + lnb[c + 2];
            float v3 = (row[c + 3] - mu) * rs * lng[c + 3] + lnb[c + 3];
            uint32_t u0 = __float_as_uint(v0), u1 = __float_as_uint(v1);
            uint32_t u2 = __float_as_uint(v2), u3 = __float_as_uint(v3);
            uint2 hp = make_uint2(__byte_perm(u0, u1, 0x7632), __byte_perm(u2, u3, 0x7632));
            __nv_bfloat162 lp0 = __float22bfloat162_rn(make_float2(
                v0 - __uint_as_float(u0 & 0xFFFF0000u), v1 - __uint_as_float(u1 & 0xFFFF0000u)));
            __nv_bfloat162 lp1 = __float22bfloat162_rn(make_float2(
                v2 - __uint_as_float(u2 & 0xFFFF0000u), v3 - __uint_as_float(u3 & 0xFFFF0000u)));
            *(uint2*)(g_qH + obase + c) = hp;
            *(uint2*)(g_qL + obase + c) = make_uint2(*(uint32_t*)&lp0, *(uint32_t*)&lp1);
        }
    }
}

// ---------------- permute f_kv -> (B,NH,D,H,W,HD) as fp16 ----------------
__global__ void k_perm(const float* __restrict__ fkv) {
    __shared__ float s[HDc * 21];
    int blk = blockIdx.x;
    int x = blk % Dim;
    int y = (blk / Dim) % Dim;
    int h = (blk / (Dim * Dim)) % NHc;
    int b = blk / (Dim * Dim * NHc);
    const float* src = fkv + ((size_t)(b * Cc + h * HDc)) * Nspat + (y * Dim + x) * Dim;
    for (int idx = threadIdx.x; idx < HDc * Dim; idx += blockDim.x) {
        int hd = idx / Dim, z = idx - hd * Dim;
        s[hd * 21 + z] = src[(size_t)hd * Nspat + z];
    }
    __syncthreads();
    __half* dst = g_feats + ((size_t)(b * NHc + h) * Nspat) * HDc;
    for (int idx = threadIdx.x; idx < HDc * Dim; idx += blockDim.x) {
        int z = idx / HDc, hd = idx - z * HDc;
        dst[(size_t)((z * Dim + y) * Dim + x) * HDc + hd] = __float2half_rn(s[hd * 21 + z]);
    }
}

// ---------------- trilinear gather + fused softmax + weighted sum ----------------
__global__ void k_sample() {
    int gw   = (blockIdx.x * blockDim.x + threadIdx.x) >> 5;
    int lane = threadIdx.x & 31;
    if (gw >= MTOT * NHc) return;
    int h = gw % NHc;
    int t = gw / NHc;
    int b = t / Nspat;
    int n = t - b * Nspat;
    int y = n / (Dim * Dim);
    int x = (n / Dim) % Dim;
    int z = n % Dim;

    const float* off = g_off + (size_t)gw * NPc * 3;
    // fused softmax over the 4 logits
    float4 lg = ((const float4*)g_attn)[gw];
    float mx = fmaxf(fmaxf(lg.x, lg.y), fmaxf(lg.z, lg.w));
    float e0 = __expf(lg.x - mx), e1 = __expf(lg.y - mx);
    float e2 = __expf(lg.z - mx), e3 = __expf(lg.w - mx);
    float inv = 1.f / (e0 + e1 + e2 + e3);
    float aw[4] = {e0 * inv, e1 * inv, e2 * inv, e3 * inv};

    const __half* feats = g_feats + ((size_t)(b * NHc + h) * Nspat) * HDc;

    float acc0 = 0.f, acc1 = 0.f;
    #pragma unroll
    for (int p = 0; p < NPc; ++p) {
        float ap = aw[p];
        float ix = fminf(fmaxf((float)y + off[p * 3 + 0], 0.f), (float)(Dim - 1));
        float iy = fminf(fmaxf((float)x + off[p * 3 + 1], 0.f), (float)(Dim - 1));
        float iz = fminf(fmaxf((float)z + off[p * 3 + 2], 0.f), (float)(Dim - 1));
        float x0f = floorf(ix), y0f = floorf(iy), z0f = floorf(iz);
        float fx = ix - x0f, fy = iy - y0f, fz = iz - z0f;
        int x0 = (int)x0f, y0 = (int)y0f, z0 = (int)z0f;
        int x1 = min(x0 + 1, Dim - 1);
        int y1 = min(y0 + 1, Dim - 1);
        int z1 = min(z0 + 1, Dim - 1);
        float wx[2] = {1.f - fx, fx};
        float wy[2] = {1.f - fy, fy};
        float wz[2] = {1.f - fz, fz};
        int   xs[2] = {x0, x1}, ys[2] = {y0, y1}, zs[2] = {z0, z1};
        #pragma unroll
        for (int dz = 0; dz < 2; ++dz)
            #pragma unroll
            for (int dy = 0; dy < 2; ++dy)
                #pragma unroll
                for (int dx = 0; dx < 2; ++dx) {
                    float w = ap * wz[dz] * wy[dy] * wx[dx];
                    const __half2* f = (const __half2*)(feats + (size_t)((zs[dz] * Dim + ys[dy]) * Dim + xs[dx]) * HDc);
                    float2 v = __half22float2(f[lane]);
                    acc0 += w * v.x;
                    acc1 += w * v.y;
                }
    }
    size_t oidx = (size_t)t * Cc + h * HDc + lane * 2;
    uint32_t u0 = __float_as_uint(acc0), u1 = __float_as_uint(acc1);
    uint32_t hp = __byte_perm(u0, u1, 0x7632);
    __nv_bfloat162 lp = __float22bfloat162_rn(make_float2(
        acc0 - __uint_as_float(u0 & 0xFFFF0000u), acc1 - __uint_as_float(u1 & 0xFFFF0000u)));
    *(uint32_t*)(g_sH + oidx) = hp;
    *(uint32_t*)(g_sL + oidx) = *(uint32_t*)&lp;
}

// ---------------- host ----------------
extern "C" void kernel_launch(void* const* d_in, const int* in_sizes, int n_in,
                              void* d_out, int out_size) {
    (void)in_sizes; (void)n_in; (void)out_size;
    const float* f_query = (const float*)d_in[0];
    const float* f_kv    = (const float*)d_in[1];
    const float* ln_g    = (const float*)d_in[2];
    const float* ln_b    = (const float*)d_in[3];
    const float* Wq   = (const float*)d_in[4];
    const float* bq   = (const float*)d_in[5];
    const float* Wo1  = (const float*)d_in[6];
    const float* bo1  = (const float*)d_in[7];
    const float* Wo2  = (const float*)d_in[8];
    const float* bo2  = (const float*)d_in[9];
    const float* Wa   = (const float*)d_in[10];
    const float* ba   = (const float*)d_in[11];
    const float* Wout = (const float*)d_in[12];
    const float* bout = (const float*)d_in[13];
    float* out = (float*)d_out;

    float *p_off, *p_attn;
    cudaGetSymbolAddress((void**)&p_off,  g_off);
    cudaGetSymbolAddress((void**)&p_attn, g_attn);
    __nv_bfloat16 *qH, *qL, *QH, *QL, *hH, *hL, *sH, *sL;
    cudaGetSymbolAddress((void**)&qH, g_qH);   cudaGetSymbolAddress((void**)&qL, g_qL);
    cudaGetSymbolAddress((void**)&QH, g_QH);   cudaGetSymbolAddress((void**)&QL, g_QL);
    cudaGetSymbolAddress((void**)&hH, g_hidH); cudaGetSymbolAddress((void**)&hL, g_hidL);
    cudaGetSymbolAddress((void**)&sH, g_sH);   cudaGetSymbolAddress((void**)&sL, g_sL);
    __nv_bfloat16 *wqH, *wqL, *wo1H, *wo1L, *wo2H, *wo2L, *waH, *waL, *woH, *woL;
    cudaGetSymbolAddress((void**)&wqH,  g_WqH);   cudaGetSymbolAddress((void**)&wqL,  g_WqL);
    cudaGetSymbolAddress((void**)&wo1H, g_Wo1H);  cudaGetSymbolAddress((void**)&wo1L, g_Wo1L);
    cudaGetSymbolAddress((void**)&wo2H, g_Wo2H);  cudaGetSymbolAddress((void**)&wo2L, g_Wo2L);
    cudaGetSymbolAddress((void**)&waH,  g_WaH);   cudaGetSymbolAddress((void**)&waL,  g_WaL);
    cudaGetSymbolAddress((void**)&woH,  g_WoutH); cudaGetSymbolAddress((void**)&woL,  g_WoutL);

    cudaFuncSetAttribute(k_sgemm<0,2>, cudaFuncAttributeMaxDynamicSharedMemorySize, MG_SMEM);
    cudaFuncSetAttribute(k_sgemm<1,2>, cudaFuncAttributeMaxDynamicSharedMemorySize, MG_SMEM);
    cudaFuncSetAttribute(k_sgemm<0,1>, cudaFuncAttributeMaxDynamicSharedMemorySize, MG_SMEM);
    cudaFuncSetAttribute(k_sgemm_dual, cudaFuncAttributeMaxDynamicSharedMemorySize, MG_SMEM);
    const int LN_SMEM = (32 * 513 + 64) * 4;
    cudaFuncSetAttribute(k_lnfuse, cudaFuncAttributeMaxDynamicSharedMemorySize, LN_SMEM);

    // merged weight prep (transpose + split) — one launch
    WPrepDesc w0{Wq,   wqH,  wqL,  512, 512};
    WPrepDesc w1{Wo1,  wo1H, wo1L, 512, 512};
    WPrepDesc w2{Wout, woH,  woL,  512, 512};
    WPrepDesc w3{Wo2,  wo2H, wo2L, NHc * NPc * 3, 128};
    WPrepDesc w4{Wa,   waH,  waL,  NHc * NPc, 128};
    k_wprep_all<<<dim3(16, 16, 5), dim3(32, 8)>>>(w0, w1, w2, w3, w4);

    // fused stats + transpose + LN -> split q
    k_lnfuse<<<dim3(250, Bc), 256, LN_SMEM>>>(f_query, ln_g, ln_b);
    // permute KV to fp16 channels-last
    k_perm<<<Bc * NHc * Dim * Dim, 256>>>(f_kv);
    // Q = q @ Wq + bq  -> split
    k_sgemm<0,2><<<dim3(4, 125), 256, MG_SMEM>>>(qH, qL, wqH, wqL, bq, nullptr, QH, QL, Cc);
    // hid = relu(Q @ Wo1 + bo1) -> split
    k_sgemm<1,2><<<dim3(4, 125), 256, MG_SMEM>>>(QH, QL, wo1H, wo1L, bo1, nullptr, hH, hL, Cc);
    // off = clip(hid @ Wo2 + bo2) AND attn logits = Q @ Wa + ba (one wave)
    k_sgemm_dual<<<dim3(1, 250), 256, MG_SMEM>>>(hH, hL, wo2H, wo2L, bo2, p_off, NHc * NPc * 3,
                                                 QH, QL, waH,  waL,  ba,  p_attn, NHc * NPc);
    // sampling (softmax fused) -> split samp
    k_sample<<<(MTOT * NHc) * 32 / 256, 256>>>();
    // out = samp @ Wout + bout, transposed fp32 store
    k_sgemm<0,1><<<dim3(4, 125), 256, MG_SMEM>>>(sH, sL, woH, woL, bout, out, nullptr, nullptr, Cc);
}